// round 4
// baseline (speedup 1.0000x reference)
#include <cuda_runtime.h>
#include <math.h>

// ---------------- problem constants ----------------
#define S_   8192
#define H_   16
#define D_   128
#define HD_  2048
#define C_   12
#define MP_  12
#define CTX_ 24
#define POS_ 13
#define NBLK_ 683          // ceil(8192/12)

// scratch (device globals: allocation-free rule)
__device__ float g_q[(size_t)S_ * HD_];
__device__ float g_k[(size_t)S_ * HD_];
__device__ float g_v[(size_t)S_ * HD_];
__device__ float g_ctx[(size_t)S_ * HD_];
__device__ float g_relk[(size_t)POS_ * HD_];

// ---------------- SGEMM: C[M,N] = A[M,K] @ B[K,N], row-major fp32 ----------------
// 128x128 tile, BK=8, 256 threads, 8x8 per thread.
__global__ __launch_bounds__(256, 2)
void sgemm128(const float* __restrict__ A, const float* __restrict__ B,
              float* __restrict__ Cmat, int M, int N, int K)
{
    __shared__ __align__(16) float As[8][128];
    __shared__ __align__(16) float Bs[8][128];

    const int tid  = threadIdx.x;
    const int brow = blockIdx.y * 128;
    const int bcol = blockIdx.x * 128;
    const int tx = (tid & 15) * 8;      // col offset within tile
    const int ty = (tid >> 4) * 8;      // row offset within tile

    const int arow = tid >> 1;          // 0..127
    const int acol = (tid & 1) * 4;     // 0 or 4
    const int bkr  = tid >> 5;          // 0..7
    const int bc4  = (tid & 31) * 4;    // 0..124

    const float* Ap = A + (size_t)(brow + arow) * K + acol;
    const float* Bp = B + (size_t)bkr * N + bcol + bc4;
    const bool aval = (brow + arow) < M;

    float acc[8][8];
#pragma unroll
    for (int i = 0; i < 8; i++)
#pragma unroll
        for (int j = 0; j < 8; j++) acc[i][j] = 0.f;

    for (int kt = 0; kt < K; kt += 8) {
        float4 av = aval ? *(const float4*)(Ap + kt) : make_float4(0.f, 0.f, 0.f, 0.f);
        float4 bv = *(const float4*)(Bp + (size_t)kt * N);

        __syncthreads();
        As[acol + 0][arow] = av.x;
        As[acol + 1][arow] = av.y;
        As[acol + 2][arow] = av.z;
        As[acol + 3][arow] = av.w;
        *(float4*)&Bs[bkr][bc4] = bv;
        __syncthreads();

#pragma unroll
        for (int kk = 0; kk < 8; kk++) {
            float4 a0 = *(const float4*)&As[kk][ty];
            float4 a1 = *(const float4*)&As[kk][ty + 4];
            float4 b0 = *(const float4*)&Bs[kk][tx];
            float4 b1 = *(const float4*)&Bs[kk][tx + 4];
            float a[8] = {a0.x, a0.y, a0.z, a0.w, a1.x, a1.y, a1.z, a1.w};
            float b[8] = {b0.x, b0.y, b0.z, b0.w, b1.x, b1.y, b1.z, b1.w};
#pragma unroll
            for (int i = 0; i < 8; i++)
#pragma unroll
                for (int j = 0; j < 8; j++) acc[i][j] = fmaf(a[i], b[j], acc[i][j]);
        }
    }

#pragma unroll
    for (int i = 0; i < 8; i++) {
        int row = brow + ty + i;
        if (row < M) {
            float4* cp = (float4*)(Cmat + (size_t)row * N + bcol + tx);
            cp[0] = make_float4(acc[i][0], acc[i][1], acc[i][2], acc[i][3]);
            cp[1] = make_float4(acc[i][4], acc[i][5], acc[i][6], acc[i][7]);
        }
    }
}

// ---------------- chunked attention: one block per (n, h) ----------------
__global__ __launch_bounds__(128)
void attn_kernel(const float* __restrict__ q, const float* __restrict__ k,
                 const float* __restrict__ v, const float* __restrict__ relk,
                 const float* __restrict__ pds, float* __restrict__ ctx)
{
    __shared__ float qs[C_][D_ + 1];
    __shared__ float ks[CTX_][D_ + 1];
    __shared__ float vs[CTX_][D_ + 1];
    __shared__ float rks[POS_][D_ + 1];
    __shared__ float ac[C_][CTX_ + 1];
    __shared__ float bd[C_][POS_ + 1];
    __shared__ float pr[C_][CTX_ + 1];

    const int n = blockIdx.x;
    const int h = blockIdx.y;
    const int tid = threadIdx.x;   // 0..127 == d

    // q scale: head_dim^-0.5 * log2(e) * softplus(per_dim_scale[d])
    const float qscale = 0.08838834764831845f * 1.4426950408889634f
                       * log1pf(expf(pds[tid]));

    // loads
#pragma unroll
    for (int c = 0; c < C_; c++) {
        int t = n * C_ + c;
        qs[c][tid] = (t < S_) ? q[(size_t)t * HD_ + h * D_ + tid] * qscale : 0.f;
    }
#pragma unroll
    for (int j = 0; j < CTX_; j++) {
        int p = n * C_ + j - MP_;
        bool ok = (p >= 0) && (p < S_);
        size_t off = (size_t)p * HD_ + h * D_ + tid;
        ks[j][tid] = ok ? k[off] : 0.f;
        vs[j][tid] = ok ? v[off] : 0.f;
    }
#pragma unroll
    for (int p = 0; p < POS_; p++)
        rks[p][tid] = relk[(size_t)p * HD_ + h * D_ + tid];
    __syncthreads();

    // content scores ac[c][j] = qs[c] . ks[j]
    for (int slot = tid; slot < C_ * CTX_; slot += 128) {
        int c = slot / CTX_, j = slot % CTX_;
        float s = 0.f;
#pragma unroll 16
        for (int d = 0; d < D_; d++) s = fmaf(qs[c][d], ks[j][d], s);
        ac[c][j] = s;
    }
    // rel-pos scores bd[c][p] = qs[c] . rks[p]
    for (int slot = tid; slot < C_ * POS_; slot += 128) {
        int c = slot / POS_, p = slot % POS_;
        float s = 0.f;
#pragma unroll 16
        for (int d = 0; d < D_; d++) s = fmaf(qs[c][d], rks[p][d], s);
        bd[c][p] = s;
    }
    __syncthreads();

    // rel-shift + softcap + softmax (one thread per query row)
    if (tid < C_) {
        const int c = tid;
        float sr[CTX_];
        float m = -1e30f;
#pragma unroll
        for (int j = 0; j < CTX_; j++) {
            int i  = c * CTX_ + j;
            int cp = i / (CTX_ + 1);
            int pp = i % (CTX_ + 1);
            float val = ac[c][j] + ((pp < POS_) ? bd[cp][pp] : 0.f);
            val = tanhf(val * 0.02f) * 50.f;
            sr[j] = val;
            m = fmaxf(m, val);
        }
        float sum = 0.f;
#pragma unroll
        for (int j = 0; j < CTX_; j++) { sr[j] = expf(sr[j] - m); sum += sr[j]; }
        float inv = 1.f / sum;
#pragma unroll
        for (int j = 0; j < CTX_; j++) pr[c][j] = sr[j] * inv;
    }
    __syncthreads();

    // out[c][d] = sum_j pr[c][j] * vs[j][d]
#pragma unroll
    for (int c = 0; c < C_; c++) {
        int t = n * C_ + c;
        if (t >= S_) break;
        float o = 0.f;
#pragma unroll
        for (int j = 0; j < CTX_; j++) o = fmaf(pr[c][j], vs[j][tid], o);
        ctx[(size_t)t * HD_ + h * D_ + tid] = o;
    }
}

// ---------------- launch ----------------
extern "C" void kernel_launch(void* const* d_in, const int* in_sizes, int n_in,
                              void* d_out, int out_size)
{
    const float* x     = (const float*)d_in[0];  // [1,S,HD]
    const float* pe    = (const float*)d_in[1];  // [POS,HD]
    const float* Wq    = (const float*)d_in[2];
    const float* Wk    = (const float*)d_in[3];
    const float* Wv    = (const float*)d_in[4];
    const float* Wrel  = (const float*)d_in[5];
    const float* Wpost = (const float*)d_in[6];
    const float* pds   = (const float*)d_in[7];  // [D]
    float* out = (float*)d_out;

    float *pq, *pk, *pv, *pctx, *prelk;
    cudaGetSymbolAddress((void**)&pq,    g_q);
    cudaGetSymbolAddress((void**)&pk,    g_k);
    cudaGetSymbolAddress((void**)&pv,    g_v);
    cudaGetSymbolAddress((void**)&pctx,  g_ctx);
    cudaGetSymbolAddress((void**)&prelk, g_relk);

    dim3 gbig(HD_ / 128, S_ / 128);   // (16, 64)
    dim3 grel(HD_ / 128, 1);

    sgemm128<<<gbig, 256>>>(x, Wq, pq, S_, HD_, HD_);
    sgemm128<<<gbig, 256>>>(x, Wk, pk, S_, HD_, HD_);
    sgemm128<<<gbig, 256>>>(x, Wv, pv, S_, HD_, HD_);
    sgemm128<<<grel, 256>>>(pe, Wrel, prelk, POS_, HD_, HD_);

    attn_kernel<<<dim3(NBLK_, H_), 128>>>(pq, pk, pv, prelk, pds, pctx);

    sgemm128<<<gbig, 256>>>(pctx, Wpost, out, S_, HD_, HD_);
}